// round 16
// baseline (speedup 1.0000x reference)
#include <cuda_runtime.h>
#include <cstdint>

#define V_SIZE 100000
#define EDIM   128
#define BATCH  512
#define QLEN   32
#define DLEN   256
#define KNUM   21

#define QSTRIDE 33    // odd -> conflict-free transposed stores/loads
#define DSTRIDE 257   // odd -> conflict-free transposed stores/loads
#define SMEM_FLOATS (EDIM*QSTRIDE + EDIM*DSTRIDE + QLEN*KNUM)
#define SMEM_BYTES  (SMEM_FLOATS * 4)

struct KParams {
    float mu[KNUM];   // exact f32 casts of the python-f64 accumulated mus (sorted asc)
    float coef0;      // -0.5 / sigma0^2  (sigma0 = 0.1f, broad bin at mu[0])
    float coefS;      // -0.5 / sigmaS^2  (sigmaS = 0.001f, sharp bins 1..20)
};

__device__ float g_kout[2][BATCH][KNUM];

// ---------------- packed f32x2 helpers (Blackwell FFMA2 via PTX) ----------------
__device__ __forceinline__ unsigned long long pack2(float x, float y) {
    unsigned long long r;
    asm("mov.b64 %0, {%1,%2};" : "=l"(r) : "f"(x), "f"(y));
    return r;
}
__device__ __forceinline__ void unpack2(unsigned long long v, float& x, float& y) {
    asm("mov.b64 {%0,%1}, %2;" : "=f"(x), "=f"(y) : "l"(v));
}
__device__ __forceinline__ void ffma2(unsigned long long& c,
                                      unsigned long long a,
                                      unsigned long long b) {
    asm("fma.rn.f32x2 %0, %1, %2, %0;" : "+l"(c) : "l"(a), "l"(b));
}

// =====================================================================
// Kernel 1: one CTA per (batch b, pair p).
//  - gather + L2-normalize 32 q rows + 256 d rows into transposed smem
//  - 32x256 fp32 cosine GEMM via f32x2 FFMA (thread tile 4q x 8d)
//  - Gaussian kernel pooling: broad bin 0 always; only the nearest sharp
//    bin can be nonzero in fp32 (|d|<=0.0132 << bin spacing 0.1)
//  - per-q bin sums in smem, then k_out[k] = sum_q log1p(bins[q][k])
// =====================================================================
__global__ void __launch_bounds__(256, 1) knrm_main(
    const float* __restrict__ emb,
    const int*   __restrict__ q1, const int* __restrict__ d1,
    const int*   __restrict__ q2, const int* __restrict__ d2,
    KParams P)
{
    extern __shared__ float smem[];
    float* sQ    = smem;                                   // [EDIM][QSTRIDE]  (e-major, q minor)
    float* sD    = smem + EDIM * QSTRIDE;                  // [EDIM][DSTRIDE]
    float* sBins = smem + EDIM * QSTRIDE + EDIM * DSTRIDE; // [QLEN][KNUM]

    const int b = blockIdx.x;
    const int p = blockIdx.y;
    const int* __restrict__ qidx = p ? q2 : q1;
    const int* __restrict__ didx = p ? d2 : d1;

    const int tid  = threadIdx.x;
    const int lane = tid & 31;
    const int w    = tid >> 5;

    for (int i = tid; i < QLEN * KNUM; i += 256) sBins[i] = 0.0f;

    // ---- gather + normalize + transpose: 288 rows, 4 rows per warp-iter ----
    for (int it = 0; it < 9; ++it) {
        const int rbase = it * 32 + w * 4;
        float v[4][4];
        #pragma unroll
        for (int rr = 0; rr < 4; ++rr) {
            const int r = rbase + rr;
            int tok = (r < QLEN) ? qidx[b * QLEN + r] : didx[b * DLEN + (r - QLEN)];
            tok = min(max(tok, 0), V_SIZE - 1);
            const float* row = emb + (size_t)tok * EDIM + lane;
            #pragma unroll
            for (int k = 0; k < 4; ++k) v[rr][k] = row[32 * k];   // coalesced 128B
        }
        #pragma unroll
        for (int rr = 0; rr < 4; ++rr) {
            float ss = v[rr][0]*v[rr][0] + v[rr][1]*v[rr][1]
                     + v[rr][2]*v[rr][2] + v[rr][3]*v[rr][3];
            #pragma unroll
            for (int off = 16; off; off >>= 1)
                ss += __shfl_xor_sync(0xffffffffu, ss, off);
            // match reference: x / max(sqrt(ss), 1e-8), IEEE ops (fast-math-proof)
            const float scale = __fdiv_rn(1.0f, fmaxf(__fsqrt_rn(ss), 1e-8f));
            const int r = rbase + rr;
            if (r < QLEN) {
                #pragma unroll
                for (int k = 0; k < 4; ++k)
                    sQ[(lane + 32 * k) * QSTRIDE + r] = v[rr][k] * scale;
            } else {
                const int dc = r - QLEN;
                #pragma unroll
                for (int k = 0; k < 4; ++k)
                    sD[(lane + 32 * k) * DSTRIDE + dc] = v[rr][k] * scale;
            }
        }
    }
    __syncthreads();

    // ---- GEMM: thread (qg,dg) computes q rows [4qg..4qg+3] x d cols [8dg..8dg+7] ----
    const int qg = tid & 7;
    const int dg = tid >> 3;
    const int qb = qg * 4;
    const int db = dg * 8;

    unsigned long long acc[4][4];
    #pragma unroll
    for (int i = 0; i < 4; ++i)
        #pragma unroll
        for (int j = 0; j < 4; ++j) acc[i][j] = 0ull;

    #pragma unroll 4
    for (int e = 0; e < EDIM; ++e) {
        const float* qp = sQ + e * QSTRIDE + qb;
        const float* dp = sD + e * DSTRIDE + db;
        unsigned long long qd[4], dd[4];
        #pragma unroll
        for (int i = 0; i < 4; ++i) { const float qv = qp[i]; qd[i] = pack2(qv, qv); }
        #pragma unroll
        for (int j = 0; j < 4; ++j) { dd[j] = pack2(dp[2 * j], dp[2 * j + 1]); }
        #pragma unroll
        for (int i = 0; i < 4; ++i)
            #pragma unroll
            for (int j = 0; j < 4; ++j)
                ffma2(acc[i][j], qd[i], dd[j]);
    }

    // ---- pooling ----
    const float mu0 = P.mu[0];
    const float c0  = P.coef0;
    const float cS  = P.coefS;

    #pragma unroll
    for (int i = 0; i < 4; ++i) {
        float broad = 0.0f;
        #pragma unroll
        for (int j = 0; j < 4; ++j) {
            float xlo, xhi;
            unpack2(acc[i][j], xlo, xhi);
            #pragma unroll
            for (int h = 0; h < 2; ++h) {
                const float x = h ? xhi : xlo;
                // broad bin (mu ~ -0.95, sigma 0.1): always contributes
                const float d0 = x - mu0;
                broad += __expf(d0 * d0 * c0);
                // nearest sharp bin: the only one that can be nonzero in fp32
                int jj = __float2int_rn((x + 0.85f) * 10.0f);
                jj = max(0, min(18, jj));
                const int k = (x >= 0.975f) ? 20 : (jj + 1);
                const float dk = x - P.mu[k];
                const float z = dk * dk * cS;
                if (z > -88.0f)   // exp(z) < 1.2e-38 otherwise (== 0 vs O(1) sums)
                    atomicAdd(&sBins[(qb + i) * KNUM + k], __expf(z));
            }
        }
        atomicAdd(&sBins[(qb + i) * KNUM + 0], broad);
    }
    __syncthreads();

    // ---- finalize: k_out[k] = sum_q log1p(bins[q][k]) ----
    if (tid < KNUM) {
        float s = 0.0f;
        #pragma unroll
        for (int q = 0; q < QLEN; ++q)
            s += log1pf(sBins[q * KNUM + tid]);
        g_kout[p][b][tid] = s;
    }
}

// =====================================================================
// Kernel 2: per-batch MLP on both pairs + sigmoid(l1 - l2)
// =====================================================================
__global__ void __launch_bounds__(512) knrm_mlp(
    const float* __restrict__ w1, const float* __restrict__ b1,
    const float* __restrict__ w2, const float* __restrict__ b2,
    const float* __restrict__ w3, const float* __restrict__ b3,
    float* __restrict__ out)
{
    __shared__ float sW1[KNUM * 10], sB1[10], sW2[50], sB2[5], sW3[5], sB3;
    const int tid = threadIdx.x;
    if (tid < KNUM * 10) sW1[tid] = w1[tid];
    if (tid < 10)        sB1[tid] = b1[tid];
    if (tid < 50)        sW2[tid] = w2[tid];
    if (tid < 5)         sB2[tid] = b2[tid];
    if (tid < 5)         sW3[tid] = w3[tid];
    if (tid == 0)        sB3 = b3[0];
    __syncthreads();

    const int b = tid;  // 512 threads == BATCH
    float logit[2];
    #pragma unroll
    for (int p = 0; p < 2; ++p) {
        float x1[10];
        #pragma unroll
        for (int j = 0; j < 10; ++j) x1[j] = sB1[j];
        #pragma unroll
        for (int k = 0; k < KNUM; ++k) {
            const float kv = fmaxf(g_kout[p][b][k], 0.0f);
            #pragma unroll
            for (int j = 0; j < 10; ++j) x1[j] = fmaf(kv, sW1[k * 10 + j], x1[j]);
        }
        float x2[5];
        #pragma unroll
        for (int j = 0; j < 5; ++j) x2[j] = sB2[j];
        #pragma unroll
        for (int k = 0; k < 10; ++k) {
            const float kv = fmaxf(x1[k], 0.0f);
            #pragma unroll
            for (int j = 0; j < 5; ++j) x2[j] = fmaf(kv, sW2[k * 5 + j], x2[j]);
        }
        float x3 = sB3;
        #pragma unroll
        for (int k = 0; k < 5; ++k) x3 = fmaf(fmaxf(x2[k], 0.0f), sW3[k], x3);
        logit[p] = x3;
    }

    const float t = logit[0] - logit[1];
    float r;
    if (t >= 0.0f) { const float e = __expf(-t); r = 1.0f / (1.0f + e); }
    else           { const float e = __expf(t);  r = e / (1.0f + e); }
    out[b] = r;
}

// =====================================================================
extern "C" void kernel_launch(void* const* d_in, const int* in_sizes, int n_in,
                              void* d_out, int out_size)
{
    const float* emb = (const float*)d_in[0];
    const float* w1  = (const float*)d_in[1];
    const float* b1  = (const float*)d_in[2];
    const float* w2  = (const float*)d_in[3];
    const float* b2  = (const float*)d_in[4];
    const float* w3  = (const float*)d_in[5];
    const float* b3  = (const float*)d_in[6];
    const int*   q1  = (const int*)d_in[7];
    const int*   dd1 = (const int*)d_in[8];
    const int*   q2  = (const int*)d_in[9];
    const int*   dd2 = (const int*)d_in[10];

    // Replicate the python f64 mu construction exactly, then cast to f32
    KParams P;
    {
        double lmu[KNUM];
        lmu[0] = 1.0;
        const double bs = 2.0 / (double)(KNUM - 1);
        lmu[1] = 1.0 - bs * 0.5;
        for (int j = 1; j <= KNUM - 2; ++j) lmu[j + 1] = lmu[j] - bs;
        // sort ascending (21 elements, simple selection sort)
        for (int i = 0; i < KNUM; ++i)
            for (int j = i + 1; j < KNUM; ++j)
                if (lmu[j] < lmu[i]) { double t = lmu[i]; lmu[i] = lmu[j]; lmu[j] = t; }
        for (int i = 0; i < KNUM; ++i) P.mu[i] = (float)lmu[i];
        const float s0 = 0.1f, sS = 0.001f;  // sorted([0.1]+[0.001]*20, desc)
        P.coef0 = -0.5f / (s0 * s0);
        P.coefS = -0.5f / (sS * sS);
    }

    cudaFuncSetAttribute(knrm_main, cudaFuncAttributeMaxDynamicSharedMemorySize,
                         SMEM_BYTES);

    dim3 grid(BATCH, 2);
    knrm_main<<<grid, 256, SMEM_BYTES>>>(emb, q1, dd1, q2, dd2, P);
    knrm_mlp<<<1, 512>>>(w1, b1, w2, b2, w3, b3, (float*)d_out);
    (void)in_sizes; (void)n_in; (void)out_size;
}

// round 17
// speedup vs baseline: 1.0514x; 1.0514x over previous
#include <cuda_runtime.h>
#include <cstdint>

#define V_SIZE 100000
#define EDIM   128
#define BATCH  512
#define QLEN   32
#define DLEN   256
#define KNUM   21

#define QSTRIDE 33    // odd -> conflict-free transposed stores/loads
#define DSTRIDE 257   // odd -> conflict-free transposed stores/loads
#define SMEM_FLOATS (EDIM*QSTRIDE + EDIM*DSTRIDE + QLEN*KNUM)
#define SMEM_BYTES  (SMEM_FLOATS * 4)

struct KParams {
    float mu[KNUM];   // exact f32 casts of the python-f64 accumulated mus (sorted asc)
    float coef0;      // -0.5 / sigma0^2  (sigma0 = 0.1f, broad bin at mu[0])
    float coefS;      // -0.5 / sigmaS^2  (sigmaS = 0.001f, sharp bins 1..20)
};

__device__ float g_kout[2][BATCH][KNUM];

// ---------------- packed f32x2 helpers (Blackwell FFMA2 via PTX) ----------------
__device__ __forceinline__ unsigned long long pack2(float x, float y) {
    unsigned long long r;
    asm("mov.b64 %0, {%1,%2};" : "=l"(r) : "f"(x), "f"(y));
    return r;
}
__device__ __forceinline__ void unpack2(unsigned long long v, float& x, float& y) {
    asm("mov.b64 {%0,%1}, %2;" : "=f"(x), "=f"(y) : "l"(v));
}
__device__ __forceinline__ void ffma2(unsigned long long& c,
                                      unsigned long long a,
                                      unsigned long long b) {
    asm("fma.rn.f32x2 %0, %1, %2, %0;" : "+l"(c) : "l"(a), "l"(b));
}

// =====================================================================
// Kernel 1: one CTA per (batch b, pair p).
//  - gather + L2-normalize 32 q rows + 256 d rows into transposed smem
//  - 32x256 fp32 cosine GEMM via f32x2 FFMA (thread tile 4q x 8d)
//  - Gaussian kernel pooling: broad bin 0 always; only the nearest sharp
//    bin can be nonzero in fp32 (|d|<=0.0132 << bin spacing 0.1)
//  - per-q bin sums in smem, then k_out[k] = sum_q log1p(bins[q][k])
// =====================================================================
__global__ void __launch_bounds__(256, 1) knrm_main(
    const float* __restrict__ emb,
    const int*   __restrict__ q1, const int* __restrict__ d1,
    const int*   __restrict__ q2, const int* __restrict__ d2,
    KParams P)
{
    extern __shared__ float smem[];
    float* sQ    = smem;                                   // [EDIM][QSTRIDE]  (e-major, q minor)
    float* sD    = smem + EDIM * QSTRIDE;                  // [EDIM][DSTRIDE]
    float* sBins = smem + EDIM * QSTRIDE + EDIM * DSTRIDE; // [QLEN][KNUM]

    const int b = blockIdx.x;
    const int p = blockIdx.y;
    const int* __restrict__ qidx = p ? q2 : q1;
    const int* __restrict__ didx = p ? d2 : d1;

    const int tid  = threadIdx.x;
    const int lane = tid & 31;
    const int w    = tid >> 5;

    for (int i = tid; i < QLEN * KNUM; i += 256) sBins[i] = 0.0f;

    // ---- gather + normalize + transpose: 288 rows, 4 rows per warp-iter ----
    for (int it = 0; it < 9; ++it) {
        const int rbase = it * 32 + w * 4;
        float v[4][4];
        #pragma unroll
        for (int rr = 0; rr < 4; ++rr) {
            const int r = rbase + rr;
            int tok = (r < QLEN) ? qidx[b * QLEN + r] : didx[b * DLEN + (r - QLEN)];
            tok = min(max(tok, 0), V_SIZE - 1);
            const float* row = emb + (size_t)tok * EDIM + lane;
            #pragma unroll
            for (int k = 0; k < 4; ++k) v[rr][k] = row[32 * k];   // coalesced 128B
        }
        #pragma unroll
        for (int rr = 0; rr < 4; ++rr) {
            float ss = v[rr][0]*v[rr][0] + v[rr][1]*v[rr][1]
                     + v[rr][2]*v[rr][2] + v[rr][3]*v[rr][3];
            #pragma unroll
            for (int off = 16; off; off >>= 1)
                ss += __shfl_xor_sync(0xffffffffu, ss, off);
            // match reference: x / max(sqrt(ss), 1e-8), IEEE ops (fast-math-proof)
            const float scale = __fdiv_rn(1.0f, fmaxf(__fsqrt_rn(ss), 1e-8f));
            const int r = rbase + rr;
            if (r < QLEN) {
                #pragma unroll
                for (int k = 0; k < 4; ++k)
                    sQ[(lane + 32 * k) * QSTRIDE + r] = v[rr][k] * scale;
            } else {
                const int dc = r - QLEN;
                #pragma unroll
                for (int k = 0; k < 4; ++k)
                    sD[(lane + 32 * k) * DSTRIDE + dc] = v[rr][k] * scale;
            }
        }
    }
    __syncthreads();

    // ---- GEMM: thread (qg,dg) computes q rows [4qg..4qg+3] x d cols [8dg..8dg+7] ----
    const int qg = tid & 7;
    const int dg = tid >> 3;
    const int qb = qg * 4;
    const int db = dg * 8;

    unsigned long long acc[4][4];
    #pragma unroll
    for (int i = 0; i < 4; ++i)
        #pragma unroll
        for (int j = 0; j < 4; ++j) acc[i][j] = 0ull;

    #pragma unroll 4
    for (int e = 0; e < EDIM; ++e) {
        const float* qp = sQ + e * QSTRIDE + qb;
        const float* dp = sD + e * DSTRIDE + db;
        unsigned long long qd[4], dd[4];
        #pragma unroll
        for (int i = 0; i < 4; ++i) { const float qv = qp[i]; qd[i] = pack2(qv, qv); }
        #pragma unroll
        for (int j = 0; j < 4; ++j) { dd[j] = pack2(dp[2 * j], dp[2 * j + 1]); }
        #pragma unroll
        for (int i = 0; i < 4; ++i)
            #pragma unroll
            for (int j = 0; j < 4; ++j)
                ffma2(acc[i][j], qd[i], dd[j]);
    }

    // ---- pooling ----
    const float mu0 = P.mu[0];
    const float c0  = P.coef0;
    const float cS  = P.coefS;

    #pragma unroll
    for (int i = 0; i < 4; ++i) {
        float broad = 0.0f;
        #pragma unroll
        for (int j = 0; j < 4; ++j) {
            float xlo, xhi;
            unpack2(acc[i][j], xlo, xhi);
            #pragma unroll
            for (int h = 0; h < 2; ++h) {
                const float x = h ? xhi : xlo;
                // broad bin (mu ~ -0.95, sigma 0.1): always contributes
                const float d0 = x - mu0;
                broad += __expf(d0 * d0 * c0);
                // nearest sharp bin: the only one that can be nonzero in fp32
                int jj = __float2int_rn((x + 0.85f) * 10.0f);
                jj = max(0, min(18, jj));
                const int k = (x >= 0.975f) ? 20 : (jj + 1);
                const float dk = x - P.mu[k];
                const float z = dk * dk * cS;
                if (z > -88.0f)   // exp(z) < 1.2e-38 otherwise (== 0 vs O(1) sums)
                    atomicAdd(&sBins[(qb + i) * KNUM + k], __expf(z));
            }
        }
        atomicAdd(&sBins[(qb + i) * KNUM + 0], broad);
    }
    __syncthreads();

    // ---- finalize: k_out[k] = sum_q log1p(bins[q][k]) ----
    if (tid < KNUM) {
        float s = 0.0f;
        #pragma unroll
        for (int q = 0; q < QLEN; ++q)
            s += log1pf(sBins[q * KNUM + tid]);
        g_kout[p][b][tid] = s;
    }
}

// =====================================================================
// Kernel 2: per-batch MLP on both pairs + sigmoid(l1 - l2)
// =====================================================================
__global__ void __launch_bounds__(512) knrm_mlp(
    const float* __restrict__ w1, const float* __restrict__ b1,
    const float* __restrict__ w2, const float* __restrict__ b2,
    const float* __restrict__ w3, const float* __restrict__ b3,
    float* __restrict__ out)
{
    __shared__ float sW1[KNUM * 10], sB1[10], sW2[50], sB2[5], sW3[5], sB3;
    const int tid = threadIdx.x;
    if (tid < KNUM * 10) sW1[tid] = w1[tid];
    if (tid < 10)        sB1[tid] = b1[tid];
    if (tid < 50)        sW2[tid] = w2[tid];
    if (tid < 5)         sB2[tid] = b2[tid];
    if (tid < 5)         sW3[tid] = w3[tid];
    if (tid == 0)        sB3 = b3[0];
    __syncthreads();

    const int b = tid;  // 512 threads == BATCH
    float logit[2];
    #pragma unroll
    for (int p = 0; p < 2; ++p) {
        float x1[10];
        #pragma unroll
        for (int j = 0; j < 10; ++j) x1[j] = sB1[j];
        #pragma unroll
        for (int k = 0; k < KNUM; ++k) {
            const float kv = fmaxf(g_kout[p][b][k], 0.0f);
            #pragma unroll
            for (int j = 0; j < 10; ++j) x1[j] = fmaf(kv, sW1[k * 10 + j], x1[j]);
        }
        float x2[5];
        #pragma unroll
        for (int j = 0; j < 5; ++j) x2[j] = sB2[j];
        #pragma unroll
        for (int k = 0; k < 10; ++k) {
            const float kv = fmaxf(x1[k], 0.0f);
            #pragma unroll
            for (int j = 0; j < 5; ++j) x2[j] = fmaf(kv, sW2[k * 5 + j], x2[j]);
        }
        float x3 = sB3;
        #pragma unroll
        for (int k = 0; k < 5; ++k) x3 = fmaf(fmaxf(x2[k], 0.0f), sW3[k], x3);
        logit[p] = x3;
    }

    const float t = logit[0] - logit[1];
    float r;
    if (t >= 0.0f) { const float e = __expf(-t); r = 1.0f / (1.0f + e); }
    else           { const float e = __expf(t);  r = e / (1.0f + e); }
    out[b] = r;
}

// =====================================================================
extern "C" void kernel_launch(void* const* d_in, const int* in_sizes, int n_in,
                              void* d_out, int out_size)
{
    const float* emb = (const float*)d_in[0];
    const float* w1  = (const float*)d_in[1];
    const float* b1  = (const float*)d_in[2];
    const float* w2  = (const float*)d_in[3];
    const float* b2  = (const float*)d_in[4];
    const float* w3  = (const float*)d_in[5];
    const float* b3  = (const float*)d_in[6];
    const int*   q1  = (const int*)d_in[7];
    const int*   dd1 = (const int*)d_in[8];
    const int*   q2  = (const int*)d_in[9];
    const int*   dd2 = (const int*)d_in[10];

    // Replicate the python f64 mu construction exactly, then cast to f32
    KParams P;
    {
        double lmu[KNUM];
        lmu[0] = 1.0;
        const double bs = 2.0 / (double)(KNUM - 1);
        lmu[1] = 1.0 - bs * 0.5;
        for (int j = 1; j <= KNUM - 2; ++j) lmu[j + 1] = lmu[j] - bs;
        // sort ascending (21 elements, simple selection sort)
        for (int i = 0; i < KNUM; ++i)
            for (int j = i + 1; j < KNUM; ++j)
                if (lmu[j] < lmu[i]) { double t = lmu[i]; lmu[i] = lmu[j]; lmu[j] = t; }
        for (int i = 0; i < KNUM; ++i) P.mu[i] = (float)lmu[i];
        const float s0 = 0.1f, sS = 0.001f;  // sorted([0.1]+[0.001]*20, desc)
        P.coef0 = -0.5f / (s0 * s0);
        P.coefS = -0.5f / (sS * sS);
    }

    cudaFuncSetAttribute(knrm_main, cudaFuncAttributeMaxDynamicSharedMemorySize,
                         SMEM_BYTES);

    dim3 grid(BATCH, 2);
    knrm_main<<<grid, 256, SMEM_BYTES>>>(emb, q1, dd1, q2, dd2, P);
    knrm_mlp<<<1, 512>>>(w1, b1, w2, b2, w3, b3, (float*)d_out);
    (void)in_sizes; (void)n_in; (void)out_size;
}